// round 5
// baseline (speedup 1.0000x reference)
#include <cuda_runtime.h>

#define BS   256
#define FTN  8
#define ATN  264   // BS + FTN
#define NDIM 512

// Scratch (no allocations allowed): logits [256 x 264]
__device__ float g_logits[BS * ATN];

__device__ __forceinline__ void acc3(const float4& x, const float4& t,
                                     float& dot, float& in2, float& tn2)
{
    dot += x.x * t.x + x.y * t.y + x.z * t.z + x.w * t.w;
    in2 += x.x * x.x + x.y * x.y + x.z * x.z + x.w * x.w;
    tn2 += t.x * t.x + t.y * t.y + t.z * t.z + t.w * t.w;
}
__device__ __forceinline__ void acc2(const float4& x, const float4& t,
                                     float& dot, float& in2)
{
    dot += x.x * t.x + x.y * t.y + x.z * t.z + x.w * t.w;
    in2 += x.x * x.x + x.y * x.y + x.z * x.z + x.w * x.w;
}

// ---------------------------------------------------------------------------
// Kernel 1: one warp per (b-pair, a).  Rows b0=2*bp and b0+1 share text row
// rand[a] when a < 256 (halves L2 text traffic); false-text branch loads two.
// 12 (or 16) LDG.128 front-batched per warp. Image stream = evict-first.
// ---------------------------------------------------------------------------
__global__ __launch_bounds__(256) void cl_dot_kernel(
    const float* __restrict__ img,
    const float* __restrict__ rand_t,
    const float* __restrict__ false_t,
    const float* __restrict__ logit_scale,
    float* __restrict__ out)
{
    int gwarp = (blockIdx.x * blockDim.x + threadIdx.x) >> 5;
    int lane  = threadIdx.x & 31;
    if (blockIdx.x == 0 && threadIdx.x == 0) out[0] = 0.0f;
    if (gwarp >= (BS / 2) * ATN) return;

    int bp = gwarp / ATN;
    int a  = gwarp - bp * ATN;
    int b0 = 2 * bp;

    const float4* ip0 = (const float4*)(img + ((size_t)b0 * ATN + a) * NDIM);
    const float4* ip1 = (const float4*)(img + ((size_t)(b0 + 1) * ATN + a) * NDIM);

    float dot0 = 0.f, dot1 = 0.f, in20 = 0.f, in21 = 0.f, tn20 = 0.f, tn21 = 0.f;

    if (a < BS) {
        const float4* tp = (const float4*)(rand_t + (size_t)a * NDIM);
        // Front-batched: 12 independent LDG.128.
        float4 xa0 = __ldcs(ip0 + lane);
        float4 xa1 = __ldcs(ip0 + lane + 32);
        float4 xa2 = __ldcs(ip0 + lane + 64);
        float4 xa3 = __ldcs(ip0 + lane + 96);
        float4 xb0 = __ldcs(ip1 + lane);
        float4 xb1 = __ldcs(ip1 + lane + 32);
        float4 xb2 = __ldcs(ip1 + lane + 64);
        float4 xb3 = __ldcs(ip1 + lane + 96);
        float4 t0  = __ldg(tp + lane);
        float4 t1  = __ldg(tp + lane + 32);
        float4 t2  = __ldg(tp + lane + 64);
        float4 t3  = __ldg(tp + lane + 96);

        acc3(xa0, t0, dot0, in20, tn20);
        acc3(xa1, t1, dot0, in20, tn20);
        acc3(xa2, t2, dot0, in20, tn20);
        acc3(xa3, t3, dot0, in20, tn20);
        acc2(xb0, t0, dot1, in21);
        acc2(xb1, t1, dot1, in21);
        acc2(xb2, t2, dot1, in21);
        acc2(xb3, t3, dot1, in21);
        tn21 = tn20;
    } else {
        const float4* tp0 = (const float4*)(false_t + ((size_t)b0 * FTN + (a - BS)) * NDIM);
        const float4* tp1 = (const float4*)(false_t + ((size_t)(b0 + 1) * FTN + (a - BS)) * NDIM);
        float4 xa0 = __ldcs(ip0 + lane);
        float4 xa1 = __ldcs(ip0 + lane + 32);
        float4 xa2 = __ldcs(ip0 + lane + 64);
        float4 xa3 = __ldcs(ip0 + lane + 96);
        float4 xb0 = __ldcs(ip1 + lane);
        float4 xb1 = __ldcs(ip1 + lane + 32);
        float4 xb2 = __ldcs(ip1 + lane + 64);
        float4 xb3 = __ldcs(ip1 + lane + 96);
        float4 t0  = __ldg(tp0 + lane);
        float4 t1  = __ldg(tp0 + lane + 32);
        float4 t2  = __ldg(tp0 + lane + 64);
        float4 t3  = __ldg(tp0 + lane + 96);
        float4 u0  = __ldg(tp1 + lane);
        float4 u1  = __ldg(tp1 + lane + 32);
        float4 u2  = __ldg(tp1 + lane + 64);
        float4 u3  = __ldg(tp1 + lane + 96);

        acc3(xa0, t0, dot0, in20, tn20);
        acc3(xa1, t1, dot0, in20, tn20);
        acc3(xa2, t2, dot0, in20, tn20);
        acc3(xa3, t3, dot0, in20, tn20);
        acc3(xb0, u0, dot1, in21, tn21);
        acc3(xb1, u1, dot1, in21, tn21);
        acc3(xb2, u2, dot1, in21, tn21);
        acc3(xb3, u3, dot1, in21, tn21);
    }

    #pragma unroll
    for (int o = 16; o > 0; o >>= 1) {
        dot0 += __shfl_xor_sync(0xffffffffu, dot0, o);
        dot1 += __shfl_xor_sync(0xffffffffu, dot1, o);
        in20 += __shfl_xor_sync(0xffffffffu, in20, o);
        in21 += __shfl_xor_sync(0xffffffffu, in21, o);
        tn20 += __shfl_xor_sync(0xffffffffu, tn20, o);
        tn21 += __shfl_xor_sync(0xffffffffu, tn21, o);
    }
    if (lane == 0) {
        float scale = expf(logit_scale[0]);
        g_logits[(size_t)b0 * ATN + a]       = scale * dot0 * rsqrtf(in20 * tn20);
        g_logits[(size_t)(b0 + 1) * ATN + a] = scale * dot1 * rsqrtf(in21 * tn21);
    }
}

// ---------------------------------------------------------------------------
// Kernel 2: one warp per CE term, no __syncthreads.
//   warp r in [0,256):    image term  lse(logits[r, 0:264]) - logits[r,r]
//   warp 256+a:           text  term  lse(logits[0:256, a]) - logits[a,a]
// Shuffle reductions only; atomicAdd accumulates (term / 512) into out[0].
// ---------------------------------------------------------------------------
__global__ __launch_bounds__(256) void cl_lse_kernel(float* __restrict__ out)
{
    int gw   = (blockIdx.x * blockDim.x + threadIdx.x) >> 5;
    int lane = threadIdx.x & 31;
    if (gw >= 2 * BS) return;

    float v[9];
    float diag;
    if (gw < BS) {
        const float* row = g_logits + (size_t)gw * ATN;
        #pragma unroll
        for (int i = 0; i < 8; i++) v[i] = row[lane + 32 * i];
        v[8] = (lane < FTN) ? row[BS + lane] : -1e30f;
        diag = row[gw];
    } else {
        int a = gw - BS;
        #pragma unroll
        for (int i = 0; i < 8; i++) v[i] = g_logits[(size_t)(lane + 32 * i) * ATN + a];
        v[8] = -1e30f;
        diag = g_logits[(size_t)a * ATN + a];
    }

    float m = v[0];
    #pragma unroll
    for (int i = 1; i < 9; i++) m = fmaxf(m, v[i]);
    #pragma unroll
    for (int o = 16; o > 0; o >>= 1)
        m = fmaxf(m, __shfl_xor_sync(0xffffffffu, m, o));

    float s = 0.f;
    #pragma unroll
    for (int i = 0; i < 9; i++) s += expf(v[i] - m);   // exp(-1e30 - m) == 0
    #pragma unroll
    for (int o = 16; o > 0; o >>= 1)
        s += __shfl_xor_sync(0xffffffffu, s, o);

    if (lane == 0) {
        float term = m + logf(s) - diag;
        atomicAdd(out, term * (1.0f / (2.0f * BS)));
    }
}

extern "C" void kernel_launch(void* const* d_in, const int* in_sizes, int n_in,
                              void* d_out, int out_size)
{
    const float* img     = (const float*)d_in[0];  // [256, 264, 512]
    const float* rand_t  = (const float*)d_in[1];  // [256, 512]
    const float* false_t = (const float*)d_in[2];  // [2048, 512]
    const float* lscale  = (const float*)d_in[3];  // [1]
    float* out = (float*)d_out;

    const int nwarps1 = (BS / 2) * ATN;            // 33792
    const int tpb = 256;
    const int nblocks1 = (nwarps1 * 32 + tpb - 1) / tpb;  // 4224

    cl_dot_kernel<<<nblocks1, tpb>>>(img, rand_t, false_t, lscale, out);

    const int nwarps2 = 2 * BS;                    // 512
    const int nblocks2 = (nwarps2 * 32 + tpb - 1) / tpb;  // 64
    cl_lse_kernel<<<nblocks2, tpb>>>(out);
}

// round 6
// speedup vs baseline: 1.0702x; 1.0702x over previous
#include <cuda_runtime.h>

#define BS   256
#define FTN  8
#define ATN  264   // BS + FTN
#define NDIM 512

// Scratch (no allocations allowed): logits [256 x 264] + transposed square part
__device__ float g_logits[BS * ATN];
__device__ float g_logitsT[BS * BS];   // g_logitsT[a*BS + b] = logits[b, a], a < 256

__device__ __forceinline__ void acc3(const float4& x, const float4& t,
                                     float& dot, float& in2, float& tn2)
{
    dot += x.x * t.x + x.y * t.y + x.z * t.z + x.w * t.w;
    in2 += x.x * x.x + x.y * x.y + x.z * x.z + x.w * x.w;
    tn2 += t.x * t.x + t.y * t.y + t.z * t.z + t.w * t.w;
}

// ---------------------------------------------------------------------------
// Kernel 1 (R4 winning form): one warp per (b, a) row.
//   logits[b,a] = exp(logit_scale) * dot(img[b,a], text) / (||img|| * ||text||)
// 8 LDG.128 front-batched (MLP=8). Image = evict-first. Lane 0 writes the
// logit twice: row-major and (for a<256) transposed, so the lse kernel reads
// coalesced in both directions.
// ---------------------------------------------------------------------------
__global__ __launch_bounds__(256) void cl_dot_kernel(
    const float* __restrict__ img,
    const float* __restrict__ rand_t,
    const float* __restrict__ false_t,
    const float* __restrict__ logit_scale,
    float* __restrict__ out)
{
    int gwarp = (blockIdx.x * blockDim.x + threadIdx.x) >> 5;
    int lane  = threadIdx.x & 31;
    if (blockIdx.x == 0 && threadIdx.x == 0) out[0] = 0.0f;
    if (gwarp >= BS * ATN) return;

    int b = gwarp / ATN;
    int a = gwarp - b * ATN;

    const float4* ip = (const float4*)(img + (size_t)gwarp * NDIM);
    const float*  tbase = (a < BS)
        ? (rand_t + (size_t)a * NDIM)
        : (false_t + ((size_t)b * FTN + (a - BS)) * NDIM);
    const float4* tp = (const float4*)tbase;

    float4 x0 = __ldcs(ip + lane);
    float4 x1 = __ldcs(ip + lane + 32);
    float4 x2 = __ldcs(ip + lane + 64);
    float4 x3 = __ldcs(ip + lane + 96);
    float4 t0 = __ldg(tp + lane);
    float4 t1 = __ldg(tp + lane + 32);
    float4 t2 = __ldg(tp + lane + 64);
    float4 t3 = __ldg(tp + lane + 96);

    float dot = 0.f, in2 = 0.f, tn2 = 0.f;
    acc3(x0, t0, dot, in2, tn2);
    acc3(x1, t1, dot, in2, tn2);
    acc3(x2, t2, dot, in2, tn2);
    acc3(x3, t3, dot, in2, tn2);

    #pragma unroll
    for (int o = 16; o > 0; o >>= 1) {
        dot += __shfl_xor_sync(0xffffffffu, dot, o);
        in2 += __shfl_xor_sync(0xffffffffu, in2, o);
        tn2 += __shfl_xor_sync(0xffffffffu, tn2, o);
    }
    if (lane == 0) {
        float scale = expf(logit_scale[0]);
        float lg = scale * dot * rsqrtf(in2 * tn2);
        g_logits[gwarp] = lg;
        if (a < BS) g_logitsT[(size_t)a * BS + b] = lg;
    }
}

// ---------------------------------------------------------------------------
// Kernel 2: one warp per CE term, all loads coalesced, no __syncthreads.
//   warp r in [0,256):    image term  lse(logits[r, :]) - logits[r,r]
//   warp 256+a:           text  term  lse(logitsT[a, :]) - logitsT[a,a]
// ---------------------------------------------------------------------------
__global__ __launch_bounds__(256) void cl_lse_kernel(float* __restrict__ out)
{
    int gw   = (blockIdx.x * blockDim.x + threadIdx.x) >> 5;
    int lane = threadIdx.x & 31;
    if (gw >= 2 * BS) return;

    float v[9];
    float diag;
    if (gw < BS) {
        const float* row = g_logits + (size_t)gw * ATN;
        #pragma unroll
        for (int i = 0; i < 8; i++) v[i] = row[lane + 32 * i];
        v[8] = (lane < FTN) ? row[BS + lane] : -1e30f;
        diag = row[gw];
    } else {
        int a = gw - BS;
        const float* row = g_logitsT + (size_t)a * BS;
        #pragma unroll
        for (int i = 0; i < 8; i++) v[i] = row[lane + 32 * i];
        v[8] = -1e30f;
        diag = row[a];
    }

    float m = v[0];
    #pragma unroll
    for (int i = 1; i < 9; i++) m = fmaxf(m, v[i]);
    #pragma unroll
    for (int o = 16; o > 0; o >>= 1)
        m = fmaxf(m, __shfl_xor_sync(0xffffffffu, m, o));

    float s = 0.f;
    #pragma unroll
    for (int i = 0; i < 9; i++) s += expf(v[i] - m);   // exp(-1e30 - m) == 0
    #pragma unroll
    for (int o = 16; o > 0; o >>= 1)
        s += __shfl_xor_sync(0xffffffffu, s, o);

    if (lane == 0) {
        float term = m + logf(s) - diag;
        atomicAdd(out, term * (1.0f / (2.0f * BS)));
    }
}

extern "C" void kernel_launch(void* const* d_in, const int* in_sizes, int n_in,
                              void* d_out, int out_size)
{
    const float* img     = (const float*)d_in[0];  // [256, 264, 512]
    const float* rand_t  = (const float*)d_in[1];  // [256, 512]
    const float* false_t = (const float*)d_in[2];  // [2048, 512]
    const float* lscale  = (const float*)d_in[3];  // [1]
    float* out = (float*)d_out;

    const int nwarps1 = BS * ATN;                   // 67584
    const int tpb = 256;
    const int nblocks1 = (nwarps1 * 32 + tpb - 1) / tpb;  // 8448

    cl_dot_kernel<<<nblocks1, tpb>>>(img, rand_t, false_t, lscale, out);

    const int nwarps2 = 2 * BS;                     // 512
    const int nblocks2 = (nwarps2 * 32 + tpb - 1) / tpb;  // 64
    cl_lse_kernel<<<nblocks2, tpb>>>(out);
}

// round 7
// speedup vs baseline: 1.0713x; 1.0011x over previous
#include <cuda_runtime.h>

#define BS   256
#define FTN  8
#define ATN  264   // BS + FTN
#define NDIM 512

// Scratch (no allocations allowed): logits [256 x 264] + transposed square part
__device__ float g_logits[BS * ATN];
__device__ float g_logitsT[BS * BS];   // g_logitsT[a*BS + b] = logits[b, a], a < 256

__device__ __forceinline__ void acc3(const float4& x, const float4& t,
                                     float& dot, float& in2, float& tn2)
{
    dot += x.x * t.x + x.y * t.y + x.z * t.z + x.w * t.w;
    in2 += x.x * x.x + x.y * x.y + x.z * x.z + x.w * x.w;
    tn2 += t.x * t.x + t.y * t.y + t.z * t.z + t.w * t.w;
}

// ---------------------------------------------------------------------------
// Kernel 1 (measured-best form): one warp per (b, a) row.
//   logits[b,a] = exp(logit_scale) * dot(img[b,a], text) / (||img|| * ||text||)
// 8 LDG.128 front-batched (MLP=8). Image = evict-first. Lane 0 writes the
// logit row-major and (a<256) transposed for coalesced column lse.
// ---------------------------------------------------------------------------
__global__ __launch_bounds__(256) void cl_dot_kernel(
    const float* __restrict__ img,
    const float* __restrict__ rand_t,
    const float* __restrict__ false_t,
    const float* __restrict__ logit_scale,
    float* __restrict__ out)
{
    int gwarp = (blockIdx.x * blockDim.x + threadIdx.x) >> 5;
    int lane  = threadIdx.x & 31;
    if (blockIdx.x == 0 && threadIdx.x == 0) out[0] = 0.0f;
    if (gwarp >= BS * ATN) return;

    int b = gwarp / ATN;
    int a = gwarp - b * ATN;

    const float4* ip = (const float4*)(img + (size_t)gwarp * NDIM);
    const float*  tbase = (a < BS)
        ? (rand_t + (size_t)a * NDIM)
        : (false_t + ((size_t)b * FTN + (a - BS)) * NDIM);
    const float4* tp = (const float4*)tbase;

    float4 x0 = __ldcs(ip + lane);
    float4 x1 = __ldcs(ip + lane + 32);
    float4 x2 = __ldcs(ip + lane + 64);
    float4 x3 = __ldcs(ip + lane + 96);
    float4 t0 = __ldg(tp + lane);
    float4 t1 = __ldg(tp + lane + 32);
    float4 t2 = __ldg(tp + lane + 64);
    float4 t3 = __ldg(tp + lane + 96);

    float dot = 0.f, in2 = 0.f, tn2 = 0.f;
    acc3(x0, t0, dot, in2, tn2);
    acc3(x1, t1, dot, in2, tn2);
    acc3(x2, t2, dot, in2, tn2);
    acc3(x3, t3, dot, in2, tn2);

    #pragma unroll
    for (int o = 16; o > 0; o >>= 1) {
        dot += __shfl_xor_sync(0xffffffffu, dot, o);
        in2 += __shfl_xor_sync(0xffffffffu, in2, o);
        tn2 += __shfl_xor_sync(0xffffffffu, tn2, o);
    }
    if (lane == 0) {
        float scale = expf(logit_scale[0]);
        float lg = scale * dot * rsqrtf(in2 * tn2);
        g_logits[gwarp] = lg;
        if (a < BS) g_logitsT[(size_t)a * BS + b] = lg;
    }
}

// ---------------------------------------------------------------------------
// Kernel 2: one warp per CE term, coalesced loads, block-level term
// reduction -> ONE atomicAdd per block (64 total instead of 512).
// ---------------------------------------------------------------------------
__global__ __launch_bounds__(256) void cl_lse_kernel(float* __restrict__ out)
{
    __shared__ float s_term[8];
    int gw   = (blockIdx.x * blockDim.x + threadIdx.x) >> 5;
    int wid  = threadIdx.x >> 5;
    int lane = threadIdx.x & 31;

    float v[9];
    float diag;
    if (gw < BS) {
        const float* row = g_logits + (size_t)gw * ATN;
        #pragma unroll
        for (int i = 0; i < 8; i++) v[i] = row[lane + 32 * i];
        v[8] = (lane < FTN) ? row[BS + lane] : -1e30f;
        diag = row[gw];
    } else {
        int a = gw - BS;
        const float* row = g_logitsT + (size_t)a * BS;
        #pragma unroll
        for (int i = 0; i < 8; i++) v[i] = row[lane + 32 * i];
        v[8] = -1e30f;
        diag = row[a];
    }

    float m = v[0];
    #pragma unroll
    for (int i = 1; i < 9; i++) m = fmaxf(m, v[i]);
    #pragma unroll
    for (int o = 16; o > 0; o >>= 1)
        m = fmaxf(m, __shfl_xor_sync(0xffffffffu, m, o));

    float s = 0.f;
    #pragma unroll
    for (int i = 0; i < 9; i++) s += expf(v[i] - m);   // exp(-1e30 - m) == 0
    #pragma unroll
    for (int o = 16; o > 0; o >>= 1)
        s += __shfl_xor_sync(0xffffffffu, s, o);

    if (lane == 0)
        s_term[wid] = m + logf(s) - diag;
    __syncthreads();

    // Warp 0 reduces the 8 per-warp terms; one atomic per block.
    if (wid == 0) {
        float t = (lane < 8) ? s_term[lane] : 0.f;
        #pragma unroll
        for (int o = 4; o > 0; o >>= 1)
            t += __shfl_xor_sync(0xffffffffu, t, o);
        if (lane == 0)
            atomicAdd(out, t * (1.0f / (2.0f * BS)));
    }
}

extern "C" void kernel_launch(void* const* d_in, const int* in_sizes, int n_in,
                              void* d_out, int out_size)
{
    const float* img     = (const float*)d_in[0];  // [256, 264, 512]
    const float* rand_t  = (const float*)d_in[1];  // [256, 512]
    const float* false_t = (const float*)d_in[2];  // [2048, 512]
    const float* lscale  = (const float*)d_in[3];  // [1]
    float* out = (float*)d_out;

    const int nwarps1 = BS * ATN;                   // 67584
    const int tpb = 256;
    const int nblocks1 = (nwarps1 * 32 + tpb - 1) / tpb;  // 8448

    cl_dot_kernel<<<nblocks1, tpb>>>(img, rand_t, false_t, lscale, out);

    cl_lse_kernel<<<64, tpb>>>(out);                // 512 warps = 512 CE terms
}